// round 12
// baseline (speedup 1.0000x reference)
#include <cuda_runtime.h>
#include <cuda_bf16.h>
#include <cstdint>

// Problem constants
#define BATCH 4
#define SEQ   2048
#define CIN   1024
#define C3    3072
#define NH    8
#define DH    128
#define SCALE_F 0.08838834764831845f   // 1/sqrt(128)

typedef __nv_bfloat16 bf16;

// ---------------------------------------------------------------------------
// Scratch (device globals — no runtime allocation)
// ---------------------------------------------------------------------------
__device__ bf16 g_Wq_hi[(size_t)C3 * CIN];
__device__ bf16 g_Wq_lo[(size_t)C3 * CIN];
__device__ bf16 g_Wo_hi[(size_t)CIN * CIN];
__device__ bf16 g_Wo_lo[(size_t)CIN * CIN];
__device__ bf16 g_x_hi[(size_t)BATCH * CIN * SEQ];
__device__ bf16 g_x_lo[(size_t)BATCH * CIN * SEQ];
__device__ bf16 g_qkv_hi[(size_t)BATCH * C3 * SEQ];
__device__ bf16 g_qkv_lo[(size_t)BATCH * C3 * SEQ];
__device__ float g_M[(size_t)BATCH * NH * DH * DH];
__device__ bf16 g_M_hi[(size_t)BATCH * NH * DH * DH];
__device__ bf16 g_M_lo[(size_t)BATCH * NH * DH * DH];
__device__ bf16 g_C_hi[(size_t)BATCH * CIN * SEQ];
__device__ bf16 g_C_lo[(size_t)BATCH * CIN * SEQ];

// ---------------------------------------------------------------------------
// PTX helpers (sm_80-era features: legal in compute_103 PTX)
// ---------------------------------------------------------------------------
__device__ __forceinline__ uint32_t smem_to_u32(const void* p) {
    uint32_t a;
    asm("{ .reg .u64 t; cvta.to.shared.u64 t, %1; cvt.u32.u64 %0, t; }" : "=r"(a) : "l"(p));
    return a;
}
#define LDSM_X4(r, addr) \
    asm volatile("ldmatrix.sync.aligned.m8n8.x4.shared.b16 {%0,%1,%2,%3}, [%4];" \
                 : "=r"((r)[0]), "=r"((r)[1]), "=r"((r)[2]), "=r"((r)[3]) : "r"(addr))
#define LDSM_X4_T(r, addr) \
    asm volatile("ldmatrix.sync.aligned.m8n8.x4.trans.shared.b16 {%0,%1,%2,%3}, [%4];" \
                 : "=r"((r)[0]), "=r"((r)[1]), "=r"((r)[2]), "=r"((r)[3]) : "r"(addr))
#define MMA_BF16(c, a, b0, b1) \
    asm volatile("mma.sync.aligned.m16n8k16.row.col.f32.bf16.bf16.f32 " \
                 "{%0,%1,%2,%3},{%4,%5,%6,%7},{%8,%9},{%0,%1,%2,%3};" \
                 : "+f"((c)[0]), "+f"((c)[1]), "+f"((c)[2]), "+f"((c)[3]) \
                 : "r"((a)[0]), "r"((a)[1]), "r"((a)[2]), "r"((a)[3]), "r"(b0), "r"(b1))
#define CP_ASYNC16(dst, src) \
    asm volatile("cp.async.cg.shared.global [%0], [%1], 16;" :: "r"(dst), "l"(src) : "memory")
#define CP_COMMIT() asm volatile("cp.async.commit_group;" ::: "memory")
#define CP_WAIT1()  asm volatile("cp.async.wait_group 1;" ::: "memory")
#define CP_WAIT0()  asm volatile("cp.async.wait_group 0;" ::: "memory")

// ---------------------------------------------------------------------------
// fp32 -> bf16 hi + lo(residual) split, float4 vectorized
// ---------------------------------------------------------------------------
__global__ void split_pair(const float* __restrict__ src, bf16* __restrict__ hi,
                           bf16* __restrict__ lo, int n4) {
    int i = blockIdx.x * blockDim.x + threadIdx.x;
    if (i >= n4) return;
    float4 v = reinterpret_cast<const float4*>(src)[i];
    bf16 h0 = __float2bfloat16(v.x), h1 = __float2bfloat16(v.y);
    bf16 h2 = __float2bfloat16(v.z), h3 = __float2bfloat16(v.w);
    __nv_bfloat162* hp = reinterpret_cast<__nv_bfloat162*>(hi);
    __nv_bfloat162* lp = reinterpret_cast<__nv_bfloat162*>(lo);
    hp[2 * i]     = __nv_bfloat162(h0, h1);
    hp[2 * i + 1] = __nv_bfloat162(h2, h3);
    lp[2 * i]     = __nv_bfloat162(__float2bfloat16(v.x - __bfloat162float(h0)),
                                   __float2bfloat16(v.y - __bfloat162float(h1)));
    lp[2 * i + 1] = __nv_bfloat162(__float2bfloat16(v.z - __bfloat162float(h2)),
                                   __float2bfloat16(v.w - __bfloat162float(h3)));
}

__global__ void zero_M_kernel() {
    int i = blockIdx.x * blockDim.x + threadIdx.x;
    if (i < BATCH * NH * DH * DH) g_M[i] = 0.0f;
}

// ---------------------------------------------------------------------------
// 3-pass bf16 HMMA GEMM, block 128x128, 4 warps of 64x64 (high fragment
// reuse: 16 LDSM.x4 feed 96 MMAs per k16), K-chunk 32, cp.async 2-stage,
// 128 threads/CTA, 2 CTAs/SM.
// MODE 0: qkv = Wq @ x            (B k-major/trans, EPI split)   grid(16,24,4)
// MODE 1: M  += scale * V @ K^T   (B n-major,       EPI atomic)  grid(1, 8,32)
// MODE 2: C  = M @ Q              (B k-major/trans, EPI split)   grid(16,1,32)
// MODE 3: out = Wo @ C            (B k-major/trans, EPI fp32)    grid(16, 8,4)
// ---------------------------------------------------------------------------
template <int MODE>
__global__ __launch_bounds__(128, 2) void hgemm(float* __restrict__ OutExt) {
    constexpr bool BM0   = (MODE != 1);                     // B trans (k-major) path
    constexpr int  KLEN  = (MODE == 1) ? 256 : (MODE == 2 ? 128 : 1024);
    constexpr int  LDA   = (MODE == 1) ? SEQ : (MODE == 2 ? DH : CIN);
    constexpr int  LDB   = SEQ;
    constexpr int  LDY   = (MODE == 1) ? DH : SEQ;
    constexpr uint32_t AHI = 0, ALO = 10240, BHI = 20480;
    constexpr uint32_t BT  = BM0 ? 8704u : 10240u;          // B tile bytes
    constexpr uint32_t BLO = BHI + BT;
    constexpr uint32_t STAGE = BLO + BT;
    constexpr int NIT = KLEN / 32;

    extern __shared__ char smem[];
    const uint32_t sbase = smem_to_u32(smem);
    const int tid = threadIdx.x;
    const int lane = tid & 31, wid = tid >> 5;              // 4 warps
    const int wm = wid & 1, wn = wid >> 1;                  // warp grid 2(m) x 2(n)
    const int z  = blockIdx.z;
    const int m0 = (MODE == 0 || MODE == 3) ? blockIdx.y * 128 : 0;
    const int n0 = blockIdx.x * 128;
    const int kStart = (MODE == 1) ? blockIdx.y * 256 : 0;

    const bf16 *Ahi_, *Alo_, *Bhi_, *Blo_;
    bf16 *Yhi_ = nullptr, *Ylo_ = nullptr;
    float* Yf_ = nullptr;
    if (MODE == 0) {
        Ahi_ = g_Wq_hi; Alo_ = g_Wq_lo;
        Bhi_ = g_x_hi + (size_t)z * CIN * SEQ; Blo_ = g_x_lo + (size_t)z * CIN * SEQ;
        Yhi_ = g_qkv_hi + (size_t)z * C3 * SEQ; Ylo_ = g_qkv_lo + (size_t)z * C3 * SEQ;
    } else if (MODE == 1) {
        int b = z >> 3, h = z & 7;
        size_t vo = ((size_t)b * C3 + 2 * CIN + h * DH) * SEQ;
        size_t ko = ((size_t)b * C3 + CIN + h * DH) * SEQ;
        Ahi_ = g_qkv_hi + vo; Alo_ = g_qkv_lo + vo;
        Bhi_ = g_qkv_hi + ko; Blo_ = g_qkv_lo + ko;
        Yf_  = g_M + (size_t)z * DH * DH;
    } else if (MODE == 2) {
        int b = z >> 3, h = z & 7;
        Ahi_ = g_M_hi + (size_t)z * DH * DH; Alo_ = g_M_lo + (size_t)z * DH * DH;
        size_t qo = ((size_t)b * C3 + h * DH) * SEQ;
        Bhi_ = g_qkv_hi + qo; Blo_ = g_qkv_lo + qo;
        size_t co = ((size_t)b * CIN + h * DH) * SEQ;
        Yhi_ = g_C_hi + co; Ylo_ = g_C_lo + co;
    } else {
        Ahi_ = g_Wo_hi; Alo_ = g_Wo_lo;
        Bhi_ = g_C_hi + (size_t)z * CIN * SEQ; Blo_ = g_C_lo + (size_t)z * CIN * SEQ;
        Yf_  = OutExt + (size_t)z * CIN * SEQ;
    }

    // ldmatrix base addresses (tile-relative)
    const uint32_t aAddr = (uint32_t)((wm * 64 + (lane & 15)) * 80 + (lane >> 4) * 16);
    uint32_t bAddr;
    if (BM0) {
        int seg = lane >> 3;
        bAddr = (uint32_t)(((seg & 1) * 8 + (lane & 7)) * 272 + (wn * 64 + (seg >> 1) * 8) * 2);
    } else {
        bAddr = (uint32_t)((wn * 64 + ((lane >> 4) << 3) + (lane & 7)) * 80 + ((lane >> 3) & 1) * 16);
    }

    float acc[4][8][4];
#pragma unroll
    for (int i = 0; i < 4; i++)
#pragma unroll
        for (int j = 0; j < 8; j++)
#pragma unroll
            for (int q = 0; q < 4; q++) acc[i][j][q] = 0.0f;

    auto fill = [&](int s) {
        const uint32_t sp = sbase + (uint32_t)((s & 1) * STAGE);
        const int k0 = kStart + s * 32;
#pragma unroll
        for (int t = 0; t < 4; t++) {
            int c = tid + t * 128;                 // 0..511
            int row = c >> 2, ke = (c & 3) * 8;
            size_t go = (size_t)(m0 + row) * LDA + k0 + ke;
            CP_ASYNC16(sp + AHI + (uint32_t)(row * 80 + ke * 2), Ahi_ + go);
            CP_ASYNC16(sp + ALO + (uint32_t)(row * 80 + ke * 2), Alo_ + go);
        }
        if (BM0) {
#pragma unroll
            for (int t = 0; t < 4; t++) {
                int c = tid + t * 128;
                int row = c >> 4, ne = (c & 15) * 8;
                size_t go = (size_t)(k0 + row) * LDB + n0 + ne;
                CP_ASYNC16(sp + BHI + (uint32_t)(row * 272 + ne * 2), Bhi_ + go);
                CP_ASYNC16(sp + BLO + (uint32_t)(row * 272 + ne * 2), Blo_ + go);
            }
        } else {
#pragma unroll
            for (int t = 0; t < 4; t++) {
                int c = tid + t * 128;
                int row = c >> 2, ke = (c & 3) * 8;
                size_t go = (size_t)(n0 + row) * LDB + k0 + ke;
                CP_ASYNC16(sp + BHI + (uint32_t)(row * 80 + ke * 2), Bhi_ + go);
                CP_ASYNC16(sp + BLO + (uint32_t)(row * 80 + ke * 2), Blo_ + go);
            }
        }
    };

    // prologue: 1 stage in flight
    fill(0); CP_COMMIT();

    for (int s = 0; s < NIT; s++) {
        if (s + 1 < NIT) {
            fill(s + 1); CP_COMMIT();
            CP_WAIT1();
        } else {
            CP_WAIT0();
        }
        __syncthreads();

        const uint32_t st = sbase + (uint32_t)((s & 1) * STAGE);
#pragma unroll
        for (int kk = 0; kk < 2; kk++) {
            uint32_t ah[4][4], bh[4][4];
#pragma unroll
            for (int i = 0; i < 4; i++)
                LDSM_X4(ah[i], st + AHI + aAddr + (uint32_t)(i * (16 * 80) + kk * 32));
#pragma unroll
            for (int j2 = 0; j2 < 4; j2++) {
                if (BM0) LDSM_X4_T(bh[j2], st + BHI + bAddr + (uint32_t)(kk * (16 * 272) + j2 * 32));
                else     LDSM_X4  (bh[j2], st + BHI + bAddr + (uint32_t)(j2 * (16 * 80) + kk * 32));
            }
            // pass 1: hi*hi
#pragma unroll
            for (int i = 0; i < 4; i++)
#pragma unroll
                for (int j = 0; j < 8; j++)
                    MMA_BF16(acc[i][j], ah[i], bh[j >> 1][(j & 1) * 2], bh[j >> 1][(j & 1) * 2 + 1]);
            // pass 2: lo*hi
            {
                uint32_t al[4][4];
#pragma unroll
                for (int i = 0; i < 4; i++)
                    LDSM_X4(al[i], st + ALO + aAddr + (uint32_t)(i * (16 * 80) + kk * 32));
#pragma unroll
                for (int i = 0; i < 4; i++)
#pragma unroll
                    for (int j = 0; j < 8; j++)
                        MMA_BF16(acc[i][j], al[i], bh[j >> 1][(j & 1) * 2], bh[j >> 1][(j & 1) * 2 + 1]);
            }
            // pass 3: hi*lo
            {
                uint32_t bl[4][4];
#pragma unroll
                for (int j2 = 0; j2 < 4; j2++) {
                    if (BM0) LDSM_X4_T(bl[j2], st + BLO + bAddr + (uint32_t)(kk * (16 * 272) + j2 * 32));
                    else     LDSM_X4  (bl[j2], st + BLO + bAddr + (uint32_t)(j2 * (16 * 80) + kk * 32));
                }
#pragma unroll
                for (int i = 0; i < 4; i++)
#pragma unroll
                    for (int j = 0; j < 8; j++)
                        MMA_BF16(acc[i][j], ah[i], bl[j >> 1][(j & 1) * 2], bl[j >> 1][(j & 1) * 2 + 1]);
            }
        }
        __syncthreads();
    }

    // ---- epilogue ----
    const int g = lane >> 2, t4 = lane & 3;
#pragma unroll
    for (int i = 0; i < 4; i++) {
        int m = m0 + wm * 64 + i * 16 + g;
#pragma unroll
        for (int j = 0; j < 8; j++) {
            int n = n0 + wn * 64 + j * 8 + t4 * 2;
            if (MODE == 1) {
                int ml = m - m0;
                atomicAdd(&Yf_[(size_t)ml * LDY + n],       acc[i][j][0] * SCALE_F);
                atomicAdd(&Yf_[(size_t)ml * LDY + n + 1],   acc[i][j][1] * SCALE_F);
                atomicAdd(&Yf_[(size_t)(ml + 8) * LDY + n],     acc[i][j][2] * SCALE_F);
                atomicAdd(&Yf_[(size_t)(ml + 8) * LDY + n + 1], acc[i][j][3] * SCALE_F);
            } else if (MODE == 3) {
                *reinterpret_cast<float2*>(&Yf_[(size_t)m * LDY + n]) =
                    make_float2(acc[i][j][0], acc[i][j][1]);
                *reinterpret_cast<float2*>(&Yf_[(size_t)(m + 8) * LDY + n]) =
                    make_float2(acc[i][j][2], acc[i][j][3]);
            } else {
                // split store (hi/lo bf16)
#pragma unroll
                for (int half = 0; half < 2; half++) {
                    float v0 = acc[i][j][half * 2], v1 = acc[i][j][half * 2 + 1];
                    bf16 h0 = __float2bfloat16(v0), h1 = __float2bfloat16(v1);
                    size_t off = (size_t)(m + half * 8) * LDY + n;
                    *reinterpret_cast<__nv_bfloat162*>(&Yhi_[off]) = __nv_bfloat162(h0, h1);
                    *reinterpret_cast<__nv_bfloat162*>(&Ylo_[off]) =
                        __nv_bfloat162(__float2bfloat16(v0 - __bfloat162float(h0)),
                                       __float2bfloat16(v1 - __bfloat162float(h1)));
                }
            }
        }
    }
}

#define SMEM_BM0 (2 * 37888)   // 75776
#define SMEM_BM1 (2 * 40960)   // 81920

// ---------------------------------------------------------------------------
extern "C" void kernel_launch(void* const* d_in, const int* in_sizes, int n_in,
                              void* d_out, int out_size) {
    const float* x = nullptr;
    const float* W_qkv = nullptr;
    const float* W_out = nullptr;
    for (int i = 0; i < n_in; i++) {
        if (in_sizes[i] == BATCH * CIN * SEQ)      x     = (const float*)d_in[i];
        else if (in_sizes[i] == C3 * CIN)          W_qkv = (const float*)d_in[i];
        else if (in_sizes[i] == CIN * CIN)         W_out = (const float*)d_in[i];
    }
    float* out = (float*)d_out;

    cudaFuncSetAttribute(hgemm<0>, cudaFuncAttributeMaxDynamicSharedMemorySize, SMEM_BM0);
    cudaFuncSetAttribute(hgemm<1>, cudaFuncAttributeMaxDynamicSharedMemorySize, SMEM_BM1);
    cudaFuncSetAttribute(hgemm<2>, cudaFuncAttributeMaxDynamicSharedMemorySize, SMEM_BM0);
    cudaFuncSetAttribute(hgemm<3>, cudaFuncAttributeMaxDynamicSharedMemorySize, SMEM_BM0);
    cudaFuncSetAttribute(hgemm<0>, cudaFuncAttributePreferredSharedMemoryCarveout, cudaSharedmemCarveoutMaxShared);
    cudaFuncSetAttribute(hgemm<1>, cudaFuncAttributePreferredSharedMemoryCarveout, cudaSharedmemCarveoutMaxShared);
    cudaFuncSetAttribute(hgemm<2>, cudaFuncAttributePreferredSharedMemoryCarveout, cudaSharedmemCarveoutMaxShared);
    cudaFuncSetAttribute(hgemm<3>, cudaFuncAttributePreferredSharedMemoryCarveout, cudaSharedmemCarveoutMaxShared);

    // Symbol addresses for split kernels
    bf16 *pXH, *pXL, *pMH, *pML, *pWqH, *pWqL, *pWoH, *pWoL;
    float* pM;
    cudaGetSymbolAddress((void**)&pWqH, g_Wq_hi);
    cudaGetSymbolAddress((void**)&pWqL, g_Wq_lo);
    cudaGetSymbolAddress((void**)&pWoH, g_Wo_hi);
    cudaGetSymbolAddress((void**)&pWoL, g_Wo_lo);
    cudaGetSymbolAddress((void**)&pXH,  g_x_hi);
    cudaGetSymbolAddress((void**)&pXL,  g_x_lo);
    cudaGetSymbolAddress((void**)&pM,   g_M);
    cudaGetSymbolAddress((void**)&pMH,  g_M_hi);
    cudaGetSymbolAddress((void**)&pML,  g_M_lo);

    // Input splits
    split_pair<<<(C3 * CIN / 4 + 255) / 256, 256>>>(W_qkv, pWqH, pWqL, C3 * CIN / 4);
    split_pair<<<(CIN * CIN / 4 + 255) / 256, 256>>>(W_out, pWoH, pWoL, CIN * CIN / 4);
    split_pair<<<(BATCH * CIN * SEQ / 4 + 255) / 256, 256>>>(x, pXH, pXL, BATCH * CIN * SEQ / 4);

    // QKV projection
    hgemm<0><<<dim3(SEQ / 128, C3 / 128, BATCH), 128, SMEM_BM0>>>(nullptr);

    // Linear attention core: M = scale * V K^T, then C = M Q
    zero_M_kernel<<<512, 1024>>>();
    hgemm<1><<<dim3(1, 8, BATCH * NH), 128, SMEM_BM1>>>(nullptr);
    split_pair<<<(BATCH * NH * DH * DH / 4 + 255) / 256, 256>>>(pM, pMH, pML, BATCH * NH * DH * DH / 4);
    hgemm<2><<<dim3(SEQ / 128, 1, BATCH * NH), 128, SMEM_BM0>>>(nullptr);

    // Output projection
    hgemm<3><<<dim3(SEQ / 128, CIN / 128, BATCH), 128, SMEM_BM0>>>(out);
}

// round 14
// speedup vs baseline: 1.3522x; 1.3522x over previous
#include <cuda_runtime.h>
#include <cuda_fp16.h>
#include <cstdint>

// Problem constants
#define BATCH 4
#define SEQ   2048
#define CIN   1024
#define C3    3072
#define NH    8
#define DH    128
#define SCALE_F 0.08838834764831845f   // 1/sqrt(128)

// ---------------------------------------------------------------------------
// Scratch (device globals — no runtime allocation)
// ---------------------------------------------------------------------------
__device__ __half g_Wq_hi[(size_t)C3 * CIN];
__device__ __half g_Wq_lo[(size_t)C3 * CIN];
__device__ __half g_Wo_hi[(size_t)CIN * CIN];
__device__ __half g_Wo_lo[(size_t)CIN * CIN];
__device__ __half g_x[(size_t)BATCH * CIN * SEQ];            // single fp16 (B operand)
__device__ __half g_qkv_hi[(size_t)BATCH * C3 * SEQ];        // hi: used as B (Q,K) and A-hi (V)
__device__ __half g_qkv_lo[(size_t)BATCH * C3 * SEQ];        // lo: used as A-lo (V)
__device__ float  g_M[(size_t)BATCH * NH * DH * DH];
__device__ __half g_M_hi[(size_t)BATCH * NH * DH * DH];
__device__ __half g_M_lo[(size_t)BATCH * NH * DH * DH];
__device__ __half g_C[(size_t)BATCH * CIN * SEQ];            // single fp16 (B of out-proj)

// ---------------------------------------------------------------------------
// PTX helpers (sm_80-era features: legal in compute_103 PTX)
// ---------------------------------------------------------------------------
__device__ __forceinline__ uint32_t smem_to_u32(const void* p) {
    uint32_t a;
    asm("{ .reg .u64 t; cvta.to.shared.u64 t, %1; cvt.u32.u64 %0, t; }" : "=r"(a) : "l"(p));
    return a;
}
#define LDSM_X4(r, addr) \
    asm volatile("ldmatrix.sync.aligned.m8n8.x4.shared.b16 {%0,%1,%2,%3}, [%4];" \
                 : "=r"((r)[0]), "=r"((r)[1]), "=r"((r)[2]), "=r"((r)[3]) : "r"(addr))
#define LDSM_X4_T(r, addr) \
    asm volatile("ldmatrix.sync.aligned.m8n8.x4.trans.shared.b16 {%0,%1,%2,%3}, [%4];" \
                 : "=r"((r)[0]), "=r"((r)[1]), "=r"((r)[2]), "=r"((r)[3]) : "r"(addr))
#define MMA_F16(c, a, b0, b1) \
    asm volatile("mma.sync.aligned.m16n8k16.row.col.f32.f16.f16.f32 " \
                 "{%0,%1,%2,%3},{%4,%5,%6,%7},{%8,%9},{%0,%1,%2,%3};" \
                 : "+f"((c)[0]), "+f"((c)[1]), "+f"((c)[2]), "+f"((c)[3]) \
                 : "r"((a)[0]), "r"((a)[1]), "r"((a)[2]), "r"((a)[3]), "r"(b0), "r"(b1))
#define CP_ASYNC16(dst, src) \
    asm volatile("cp.async.cg.shared.global [%0], [%1], 16;" :: "r"(dst), "l"(src) : "memory")
#define CP_COMMIT() asm volatile("cp.async.commit_group;" ::: "memory")
#define CP_WAIT1()  asm volatile("cp.async.wait_group 1;" ::: "memory")
#define CP_WAIT0()  asm volatile("cp.async.wait_group 0;" ::: "memory")

// ---------------------------------------------------------------------------
// Conversions
// ---------------------------------------------------------------------------
// fp32 -> fp16 hi + lo(residual)
__global__ void split2_h(const float* __restrict__ src, __half* __restrict__ hi,
                         __half* __restrict__ lo, int n4) {
    int i = blockIdx.x * blockDim.x + threadIdx.x;
    if (i >= n4) return;
    float4 v = reinterpret_cast<const float4*>(src)[i];
    __half h0 = __float2half_rn(v.x), h1 = __float2half_rn(v.y);
    __half h2 = __float2half_rn(v.z), h3 = __float2half_rn(v.w);
    __half2* hp = reinterpret_cast<__half2*>(hi);
    __half2* lp = reinterpret_cast<__half2*>(lo);
    hp[2 * i]     = __half2(h0, h1);
    hp[2 * i + 1] = __half2(h2, h3);
    lp[2 * i]     = __half2(__float2half_rn(v.x - __half2float(h0)),
                            __float2half_rn(v.y - __half2float(h1)));
    lp[2 * i + 1] = __half2(__float2half_rn(v.z - __half2float(h2)),
                            __float2half_rn(v.w - __half2float(h3)));
}

// fp32 -> fp16 (round only)
__global__ void round_h(const float* __restrict__ src, __half* __restrict__ dst, int n4) {
    int i = blockIdx.x * blockDim.x + threadIdx.x;
    if (i >= n4) return;
    float4 v = reinterpret_cast<const float4*>(src)[i];
    __half2* dp = reinterpret_cast<__half2*>(dst);
    dp[2 * i]     = __half2(__float2half_rn(v.x), __float2half_rn(v.y));
    dp[2 * i + 1] = __half2(__float2half_rn(v.z), __float2half_rn(v.w));
}

__global__ void zero_M_kernel() {
    int i = blockIdx.x * blockDim.x + threadIdx.x;
    if (i < BATCH * NH * DH * DH) g_M[i] = 0.0f;
}

// ---------------------------------------------------------------------------
// 2-pass fp16 HMMA GEMM: Y = (A_hi + A_lo) @ B_fp16.
// Block 128x128, 4 warps of 64x64, K-chunk 32, cp.async 2-stage, 128 thr/CTA.
// MODE 0: qkv = Wq @ x            (B k-major/trans, EPI hi+lo)   grid(16,24,4)
// MODE 1: M  += scale * V @ K^T   (B n-major,       EPI atomic)  grid(1, 8,32)
// MODE 2: C  = M @ Q              (B k-major/trans, EPI hi only) grid(16,1,32)
// MODE 3: out = Wo @ C            (B k-major/trans, EPI fp32)    grid(16, 8,4)
// ---------------------------------------------------------------------------
template <int MODE>
__global__ __launch_bounds__(128, 2) void hgemm(float* __restrict__ OutExt) {
    constexpr bool BM0   = (MODE != 1);                     // B trans (k-major) path
    constexpr int  KLEN  = (MODE == 1) ? 256 : (MODE == 2 ? 128 : 1024);
    constexpr int  LDA   = (MODE == 1) ? SEQ : (MODE == 2 ? DH : CIN);
    constexpr int  LDB   = SEQ;
    constexpr int  LDY   = (MODE == 1) ? DH : SEQ;
    constexpr uint32_t AHI = 0, ALO = 10240, BOF = 20480;
    constexpr uint32_t BT  = BM0 ? 8704u : 10240u;          // B tile bytes
    constexpr uint32_t STAGE = BOF + BT;
    constexpr int NIT = KLEN / 32;

    extern __shared__ char smem[];
    const uint32_t sbase = smem_to_u32(smem);
    const int tid = threadIdx.x;
    const int lane = tid & 31, wid = tid >> 5;              // 4 warps
    const int wm = wid & 1, wn = wid >> 1;                  // warp grid 2(m) x 2(n)
    const int z  = blockIdx.z;
    const int m0 = (MODE == 0 || MODE == 3) ? blockIdx.y * 128 : 0;
    const int n0 = blockIdx.x * 128;
    const int kStart = (MODE == 1) ? blockIdx.y * 256 : 0;

    const __half *Ahi_, *Alo_, *B_;
    __half *Yhi_ = nullptr, *Ylo_ = nullptr;
    float* Yf_ = nullptr;
    if (MODE == 0) {
        Ahi_ = g_Wq_hi; Alo_ = g_Wq_lo;
        B_   = g_x + (size_t)z * CIN * SEQ;
        Yhi_ = g_qkv_hi + (size_t)z * C3 * SEQ; Ylo_ = g_qkv_lo + (size_t)z * C3 * SEQ;
    } else if (MODE == 1) {
        int b = z >> 3, h = z & 7;
        size_t vo = ((size_t)b * C3 + 2 * CIN + h * DH) * SEQ;
        size_t ko = ((size_t)b * C3 + CIN + h * DH) * SEQ;
        Ahi_ = g_qkv_hi + vo; Alo_ = g_qkv_lo + vo;
        B_   = g_qkv_hi + ko;
        Yf_  = g_M + (size_t)z * DH * DH;
    } else if (MODE == 2) {
        int b = z >> 3, h = z & 7;
        Ahi_ = g_M_hi + (size_t)z * DH * DH; Alo_ = g_M_lo + (size_t)z * DH * DH;
        B_   = g_qkv_hi + ((size_t)b * C3 + h * DH) * SEQ;
        Yhi_ = g_C + ((size_t)b * CIN + h * DH) * SEQ;
    } else {
        Ahi_ = g_Wo_hi; Alo_ = g_Wo_lo;
        B_   = g_C + (size_t)z * CIN * SEQ;
        Yf_  = OutExt + (size_t)z * CIN * SEQ;
    }

    // ldmatrix base addresses (tile-relative)
    const uint32_t aAddr = (uint32_t)((wm * 64 + (lane & 15)) * 80 + (lane >> 4) * 16);
    uint32_t bAddr;
    if (BM0) {
        int seg = lane >> 3;
        bAddr = (uint32_t)(((seg & 1) * 8 + (lane & 7)) * 272 + (wn * 64 + (seg >> 1) * 8) * 2);
    } else {
        bAddr = (uint32_t)((wn * 64 + ((lane >> 4) << 3) + (lane & 7)) * 80 + ((lane >> 3) & 1) * 16);
    }

    float acc[4][8][4];
#pragma unroll
    for (int i = 0; i < 4; i++)
#pragma unroll
        for (int j = 0; j < 8; j++)
#pragma unroll
            for (int q = 0; q < 4; q++) acc[i][j][q] = 0.0f;

    auto fill = [&](int s) {
        const uint32_t sp = sbase + (uint32_t)((s & 1) * STAGE);
        const int k0 = kStart + s * 32;
#pragma unroll
        for (int t = 0; t < 4; t++) {
            int c = tid + t * 128;                 // 0..511
            int row = c >> 2, ke = (c & 3) * 8;
            size_t go = (size_t)(m0 + row) * LDA + k0 + ke;
            CP_ASYNC16(sp + AHI + (uint32_t)(row * 80 + ke * 2), Ahi_ + go);
            CP_ASYNC16(sp + ALO + (uint32_t)(row * 80 + ke * 2), Alo_ + go);
        }
        if (BM0) {
#pragma unroll
            for (int t = 0; t < 4; t++) {
                int c = tid + t * 128;
                int row = c >> 4, ne = (c & 15) * 8;
                size_t go = (size_t)(k0 + row) * LDB + n0 + ne;
                CP_ASYNC16(sp + BOF + (uint32_t)(row * 272 + ne * 2), B_ + go);
            }
        } else {
#pragma unroll
            for (int t = 0; t < 4; t++) {
                int c = tid + t * 128;
                int row = c >> 2, ke = (c & 3) * 8;
                size_t go = (size_t)(n0 + row) * LDB + k0 + ke;
                CP_ASYNC16(sp + BOF + (uint32_t)(row * 80 + ke * 2), B_ + go);
            }
        }
    };

    // prologue: 1 stage in flight
    fill(0); CP_COMMIT();

    for (int s = 0; s < NIT; s++) {
        if (s + 1 < NIT) {
            fill(s + 1); CP_COMMIT();
            CP_WAIT1();
        } else {
            CP_WAIT0();
        }
        __syncthreads();

        const uint32_t st = sbase + (uint32_t)((s & 1) * STAGE);
#pragma unroll
        for (int kk = 0; kk < 2; kk++) {
            uint32_t ah[4][4], bh[4][4];
#pragma unroll
            for (int i = 0; i < 4; i++)
                LDSM_X4(ah[i], st + AHI + aAddr + (uint32_t)(i * (16 * 80) + kk * 32));
#pragma unroll
            for (int j2 = 0; j2 < 4; j2++) {
                if (BM0) LDSM_X4_T(bh[j2], st + BOF + bAddr + (uint32_t)(kk * (16 * 272) + j2 * 32));
                else     LDSM_X4  (bh[j2], st + BOF + bAddr + (uint32_t)(j2 * (16 * 80) + kk * 32));
            }
            // pass 1: A_hi * B
#pragma unroll
            for (int i = 0; i < 4; i++)
#pragma unroll
                for (int j = 0; j < 8; j++)
                    MMA_F16(acc[i][j], ah[i], bh[j >> 1][(j & 1) * 2], bh[j >> 1][(j & 1) * 2 + 1]);
            // pass 2: A_lo * B
            {
                uint32_t al[4][4];
#pragma unroll
                for (int i = 0; i < 4; i++)
                    LDSM_X4(al[i], st + ALO + aAddr + (uint32_t)(i * (16 * 80) + kk * 32));
#pragma unroll
                for (int i = 0; i < 4; i++)
#pragma unroll
                    for (int j = 0; j < 8; j++)
                        MMA_F16(acc[i][j], al[i], bh[j >> 1][(j & 1) * 2], bh[j >> 1][(j & 1) * 2 + 1]);
            }
        }
        __syncthreads();
    }

    // ---- epilogue ----
    const int g = lane >> 2, t4 = lane & 3;
#pragma unroll
    for (int i = 0; i < 4; i++) {
        int m = m0 + wm * 64 + i * 16 + g;
#pragma unroll
        for (int j = 0; j < 8; j++) {
            int n = n0 + wn * 64 + j * 8 + t4 * 2;
            if (MODE == 1) {
                int ml = m - m0;
                atomicAdd(&Yf_[(size_t)ml * LDY + n],       acc[i][j][0] * SCALE_F);
                atomicAdd(&Yf_[(size_t)ml * LDY + n + 1],   acc[i][j][1] * SCALE_F);
                atomicAdd(&Yf_[(size_t)(ml + 8) * LDY + n],     acc[i][j][2] * SCALE_F);
                atomicAdd(&Yf_[(size_t)(ml + 8) * LDY + n + 1], acc[i][j][3] * SCALE_F);
            } else if (MODE == 3) {
                *reinterpret_cast<float2*>(&Yf_[(size_t)m * LDY + n]) =
                    make_float2(acc[i][j][0], acc[i][j][1]);
                *reinterpret_cast<float2*>(&Yf_[(size_t)(m + 8) * LDY + n]) =
                    make_float2(acc[i][j][2], acc[i][j][3]);
            } else if (MODE == 2) {
                // hi only (C consumed as single-fp16 B downstream)
#pragma unroll
                for (int half = 0; half < 2; half++) {
                    size_t off = (size_t)(m + half * 8) * LDY + n;
                    *reinterpret_cast<__half2*>(&Yhi_[off]) =
                        __half2(__float2half_rn(acc[i][j][half * 2]),
                                __float2half_rn(acc[i][j][half * 2 + 1]));
                }
            } else {
                // MODE 0: hi + lo (V needs the lo as MMA A operand)
#pragma unroll
                for (int half = 0; half < 2; half++) {
                    float v0 = acc[i][j][half * 2], v1 = acc[i][j][half * 2 + 1];
                    __half h0 = __float2half_rn(v0), h1 = __float2half_rn(v1);
                    size_t off = (size_t)(m + half * 8) * LDY + n;
                    *reinterpret_cast<__half2*>(&Yhi_[off]) = __half2(h0, h1);
                    *reinterpret_cast<__half2*>(&Ylo_[off]) =
                        __half2(__float2half_rn(v0 - __half2float(h0)),
                                __float2half_rn(v1 - __half2float(h1)));
                }
            }
        }
    }
}

#define SMEM_BM0 (2 * (20480 + 8704))    // 58368
#define SMEM_BM1 (2 * (20480 + 10240))   // 61440

// ---------------------------------------------------------------------------
extern "C" void kernel_launch(void* const* d_in, const int* in_sizes, int n_in,
                              void* d_out, int out_size) {
    const float* x = nullptr;
    const float* W_qkv = nullptr;
    const float* W_out = nullptr;
    for (int i = 0; i < n_in; i++) {
        if (in_sizes[i] == BATCH * CIN * SEQ)      x     = (const float*)d_in[i];
        else if (in_sizes[i] == C3 * CIN)          W_qkv = (const float*)d_in[i];
        else if (in_sizes[i] == CIN * CIN)         W_out = (const float*)d_in[i];
    }
    float* out = (float*)d_out;

    cudaFuncSetAttribute(hgemm<0>, cudaFuncAttributeMaxDynamicSharedMemorySize, SMEM_BM0);
    cudaFuncSetAttribute(hgemm<1>, cudaFuncAttributeMaxDynamicSharedMemorySize, SMEM_BM1);
    cudaFuncSetAttribute(hgemm<2>, cudaFuncAttributeMaxDynamicSharedMemorySize, SMEM_BM0);
    cudaFuncSetAttribute(hgemm<3>, cudaFuncAttributeMaxDynamicSharedMemorySize, SMEM_BM0);

    // Symbol addresses
    __half *pWqH, *pWqL, *pWoH, *pWoL, *pX, *pMH, *pML;
    float* pM;
    cudaGetSymbolAddress((void**)&pWqH, g_Wq_hi);
    cudaGetSymbolAddress((void**)&pWqL, g_Wq_lo);
    cudaGetSymbolAddress((void**)&pWoH, g_Wo_hi);
    cudaGetSymbolAddress((void**)&pWoL, g_Wo_lo);
    cudaGetSymbolAddress((void**)&pX,   g_x);
    cudaGetSymbolAddress((void**)&pM,   g_M);
    cudaGetSymbolAddress((void**)&pMH,  g_M_hi);
    cudaGetSymbolAddress((void**)&pML,  g_M_lo);

    // Input conversions
    split2_h<<<(C3 * CIN / 4 + 255) / 256, 256>>>(W_qkv, pWqH, pWqL, C3 * CIN / 4);
    split2_h<<<(CIN * CIN / 4 + 255) / 256, 256>>>(W_out, pWoH, pWoL, CIN * CIN / 4);
    round_h<<<(BATCH * CIN * SEQ / 4 + 255) / 256, 256>>>(x, pX, BATCH * CIN * SEQ / 4);

    // QKV projection
    hgemm<0><<<dim3(SEQ / 128, C3 / 128, BATCH), 128, SMEM_BM0>>>(nullptr);

    // Linear attention core: M = scale * V K^T, then C = M Q
    zero_M_kernel<<<512, 1024>>>();
    hgemm<1><<<dim3(1, 8, BATCH * NH), 128, SMEM_BM1>>>(nullptr);
    split2_h<<<(BATCH * NH * DH * DH / 4 + 255) / 256, 256>>>(pM, pMH, pML, BATCH * NH * DH * DH / 4);
    hgemm<2><<<dim3(SEQ / 128, 1, BATCH * NH), 128, SMEM_BM0>>>(nullptr);

    // Output projection
    hgemm<3><<<dim3(SEQ / 128, CIN / 128, BATCH), 128, SMEM_BM0>>>(out);
}

// round 15
// speedup vs baseline: 1.4735x; 1.0897x over previous
#include <cuda_runtime.h>
#include <cuda_fp16.h>
#include <cstdint>

// Problem constants
#define BATCH 4
#define SEQ   2048
#define CIN   1024
#define C3    3072
#define NH    8
#define DH    128
#define SCALE_F 0.08838834764831845f   // 1/sqrt(128)

// ---------------------------------------------------------------------------
// Scratch (device globals — no runtime allocation)
// ---------------------------------------------------------------------------
__device__ __half g_Wq_hi[(size_t)C3 * CIN];
__device__ __half g_Wq_lo[(size_t)C3 * CIN];
__device__ __half g_Wo_hi[(size_t)CIN * CIN];
__device__ __half g_Wo_lo[(size_t)CIN * CIN];
__device__ __half g_x[(size_t)BATCH * CIN * SEQ];            // single fp16 (B operand)
__device__ __half g_qkv_hi[(size_t)BATCH * C3 * SEQ];        // hi: B (Q,K) and A-hi (V)
__device__ __half g_qkv_lo[(size_t)BATCH * C3 * SEQ];        // lo: A-lo (V)
__device__ float  g_M[(size_t)BATCH * NH * DH * DH];
__device__ __half g_M_hi[(size_t)BATCH * NH * DH * DH];
__device__ __half g_M_lo[(size_t)BATCH * NH * DH * DH];
__device__ __half g_C[(size_t)BATCH * CIN * SEQ];            // single fp16 (B of out-proj)

// ---------------------------------------------------------------------------
// PTX helpers (sm_80-era features: legal in compute_103 PTX)
// ---------------------------------------------------------------------------
__device__ __forceinline__ uint32_t smem_to_u32(const void* p) {
    uint32_t a;
    asm("{ .reg .u64 t; cvta.to.shared.u64 t, %1; cvt.u32.u64 %0, t; }" : "=r"(a) : "l"(p));
    return a;
}
#define LDSM_X4(r, addr) \
    asm volatile("ldmatrix.sync.aligned.m8n8.x4.shared.b16 {%0,%1,%2,%3}, [%4];" \
                 : "=r"((r)[0]), "=r"((r)[1]), "=r"((r)[2]), "=r"((r)[3]) : "r"(addr))
#define LDSM_X4_T(r, addr) \
    asm volatile("ldmatrix.sync.aligned.m8n8.x4.trans.shared.b16 {%0,%1,%2,%3}, [%4];" \
                 : "=r"((r)[0]), "=r"((r)[1]), "=r"((r)[2]), "=r"((r)[3]) : "r"(addr))
#define MMA_F16(c, a, b0, b1) \
    asm volatile("mma.sync.aligned.m16n8k16.row.col.f32.f16.f16.f32 " \
                 "{%0,%1,%2,%3},{%4,%5,%6,%7},{%8,%9},{%0,%1,%2,%3};" \
                 : "+f"((c)[0]), "+f"((c)[1]), "+f"((c)[2]), "+f"((c)[3]) \
                 : "r"((a)[0]), "r"((a)[1]), "r"((a)[2]), "r"((a)[3]), "r"(b0), "r"(b1))
#define CP_ASYNC16(dst, src) \
    asm volatile("cp.async.cg.shared.global [%0], [%1], 16;" :: "r"(dst), "l"(src) : "memory")
#define CP_COMMIT() asm volatile("cp.async.commit_group;" ::: "memory")
#define CP_WAIT1()  asm volatile("cp.async.wait_group 1;" ::: "memory")
#define CP_WAIT0()  asm volatile("cp.async.wait_group 0;" ::: "memory")

// ---------------------------------------------------------------------------
// Conversions
// ---------------------------------------------------------------------------
__global__ void split2_h(const float* __restrict__ src, __half* __restrict__ hi,
                         __half* __restrict__ lo, int n4) {
    int i = blockIdx.x * blockDim.x + threadIdx.x;
    if (i >= n4) return;
    float4 v = reinterpret_cast<const float4*>(src)[i];
    __half h0 = __float2half_rn(v.x), h1 = __float2half_rn(v.y);
    __half h2 = __float2half_rn(v.z), h3 = __float2half_rn(v.w);
    __half2* hp = reinterpret_cast<__half2*>(hi);
    __half2* lp = reinterpret_cast<__half2*>(lo);
    hp[2 * i]     = __half2(h0, h1);
    hp[2 * i + 1] = __half2(h2, h3);
    lp[2 * i]     = __half2(__float2half_rn(v.x - __half2float(h0)),
                            __float2half_rn(v.y - __half2float(h1)));
    lp[2 * i + 1] = __half2(__float2half_rn(v.z - __half2float(h2)),
                            __float2half_rn(v.w - __half2float(h3)));
}

__global__ void round_h(const float* __restrict__ src, __half* __restrict__ dst, int n4) {
    int i = blockIdx.x * blockDim.x + threadIdx.x;
    if (i >= n4) return;
    float4 v = reinterpret_cast<const float4*>(src)[i];
    __half2* dp = reinterpret_cast<__half2*>(dst);
    dp[2 * i]     = __half2(__float2half_rn(v.x), __float2half_rn(v.y));
    dp[2 * i + 1] = __half2(__float2half_rn(v.z), __float2half_rn(v.w));
}

__global__ void zero_M_kernel() {
    int i = blockIdx.x * blockDim.x + threadIdx.x;
    if (i < BATCH * NH * DH * DH) g_M[i] = 0.0f;
}

// ---------------------------------------------------------------------------
// 2-pass fp16 HMMA GEMM: Y = (A_hi + A_lo) @ B_fp16.
// Block 128x128, 8 warps of 64x32 (256 thr — the config that sustains 62%+
// tensor), K-chunk 64 (4 k16 steps per stage -> half the barrier overhead),
// cp.async 2-stage, 2 CTAs/SM.
// MODE 0: qkv = Wq @ x            (B k-major/trans, EPI hi+lo)   grid(16,24,4)
// MODE 1: M  += scale * V @ K^T   (B n-major,       EPI atomic)  grid(1, 8,32)
// MODE 2: C  = M @ Q              (B k-major/trans, EPI hi only) grid(16,1,32)
// MODE 3: out = Wo @ C            (B k-major/trans, EPI fp32)    grid(16, 8,4)
// ---------------------------------------------------------------------------
template <int MODE>
__global__ __launch_bounds__(256, 2) void hgemm(float* __restrict__ OutExt) {
    constexpr bool BM0   = (MODE != 1);                     // B trans (k-major) path
    constexpr int  KLEN  = (MODE == 1) ? 256 : (MODE == 2 ? 128 : 1024);
    constexpr int  LDA   = (MODE == 1) ? SEQ : (MODE == 2 ? DH : CIN);
    constexpr int  LDB   = SEQ;
    constexpr int  LDY   = (MODE == 1) ? DH : SEQ;
    // smem layout (per stage): A_hi[128x64] str 144B, A_lo, then B
    constexpr uint32_t AHI = 0, ALO = 18432, BOF = 36864;
    constexpr uint32_t BT  = BM0 ? 17408u : 18432u;         // B tile bytes
    constexpr uint32_t STAGE = BOF + BT;                    // 54272 / 55296
    constexpr int NIT = KLEN / 64;

    extern __shared__ char smem[];
    const uint32_t sbase = smem_to_u32(smem);
    const int tid = threadIdx.x;
    const int lane = tid & 31, wid = tid >> 5;              // 8 warps
    const int wm = wid & 1, wn = wid >> 1;                  // warp grid 2(m) x 4(n)
    const int z  = blockIdx.z;
    const int m0 = (MODE == 0 || MODE == 3) ? blockIdx.y * 128 : 0;
    const int n0 = blockIdx.x * 128;
    const int kStart = (MODE == 1) ? blockIdx.y * 256 : 0;

    const __half *Ahi_, *Alo_, *B_;
    __half *Yhi_ = nullptr, *Ylo_ = nullptr;
    float* Yf_ = nullptr;
    if (MODE == 0) {
        Ahi_ = g_Wq_hi; Alo_ = g_Wq_lo;
        B_   = g_x + (size_t)z * CIN * SEQ;
        Yhi_ = g_qkv_hi + (size_t)z * C3 * SEQ; Ylo_ = g_qkv_lo + (size_t)z * C3 * SEQ;
    } else if (MODE == 1) {
        int b = z >> 3, h = z & 7;
        size_t vo = ((size_t)b * C3 + 2 * CIN + h * DH) * SEQ;
        size_t ko = ((size_t)b * C3 + CIN + h * DH) * SEQ;
        Ahi_ = g_qkv_hi + vo; Alo_ = g_qkv_lo + vo;
        B_   = g_qkv_hi + ko;
        Yf_  = g_M + (size_t)z * DH * DH;
    } else if (MODE == 2) {
        int b = z >> 3, h = z & 7;
        Ahi_ = g_M_hi + (size_t)z * DH * DH; Alo_ = g_M_lo + (size_t)z * DH * DH;
        B_   = g_qkv_hi + ((size_t)b * C3 + h * DH) * SEQ;
        Yhi_ = g_C + ((size_t)b * CIN + h * DH) * SEQ;
    } else {
        Ahi_ = g_Wo_hi; Alo_ = g_Wo_lo;
        B_   = g_C + (size_t)z * CIN * SEQ;
        Yf_  = OutExt + (size_t)z * CIN * SEQ;
    }

    // ldmatrix base addresses (tile-relative)
    // A: row stride 144 B (128 B data + 16 pad, conflict-free)
    const uint32_t aAddr = (uint32_t)((wm * 64 + (lane & 15)) * 144 + (lane >> 4) * 16);
    uint32_t bAddr;
    if (BM0) {
        int seg = lane >> 3;
        bAddr = (uint32_t)(((seg & 1) * 8 + (lane & 7)) * 272 + (wn * 32 + (seg >> 1) * 8) * 2);
    } else {
        bAddr = (uint32_t)((wn * 32 + ((lane >> 4) << 3) + (lane & 7)) * 144 + ((lane >> 3) & 1) * 16);
    }

    float acc[4][4][4];
#pragma unroll
    for (int i = 0; i < 4; i++)
#pragma unroll
        for (int j = 0; j < 4; j++)
#pragma unroll
            for (int q = 0; q < 4; q++) acc[i][j][q] = 0.0f;

    auto fill = [&](int s) {
        const uint32_t sp = sbase + (uint32_t)((s & 1) * STAGE);
        const int k0 = kStart + s * 64;
        // A hi/lo: 128 rows x 64 k = 1024 cp16 per tile
#pragma unroll
        for (int t = 0; t < 4; t++) {
            int c = tid + t * 256;                 // 0..1023
            int row = c >> 3, ke = (c & 7) * 8;
            size_t go = (size_t)(m0 + row) * LDA + k0 + ke;
            CP_ASYNC16(sp + AHI + (uint32_t)(row * 144 + ke * 2), Ahi_ + go);
            CP_ASYNC16(sp + ALO + (uint32_t)(row * 144 + ke * 2), Alo_ + go);
        }
        if (BM0) {
            // B: 64 k-rows x 128 n
#pragma unroll
            for (int t = 0; t < 4; t++) {
                int c = tid + t * 256;
                int row = c >> 4, ne = (c & 15) * 8;
                size_t go = (size_t)(k0 + row) * LDB + n0 + ne;
                CP_ASYNC16(sp + BOF + (uint32_t)(row * 272 + ne * 2), B_ + go);
            }
        } else {
            // B: 128 n-rows x 64 k
#pragma unroll
            for (int t = 0; t < 4; t++) {
                int c = tid + t * 256;
                int row = c >> 3, ke = (c & 7) * 8;
                size_t go = (size_t)(n0 + row) * LDB + k0 + ke;
                CP_ASYNC16(sp + BOF + (uint32_t)(row * 144 + ke * 2), B_ + go);
            }
        }
    };

    // prologue: 1 stage in flight
    fill(0); CP_COMMIT();

    for (int s = 0; s < NIT; s++) {
        if (s + 1 < NIT) {
            fill(s + 1); CP_COMMIT();
            CP_WAIT1();
        } else {
            CP_WAIT0();
        }
        __syncthreads();

        const uint32_t st = sbase + (uint32_t)((s & 1) * STAGE);
#pragma unroll
        for (int kk = 0; kk < 4; kk++) {
            uint32_t ah[4][4], bh[2][4];
#pragma unroll
            for (int i = 0; i < 4; i++)
                LDSM_X4(ah[i], st + AHI + aAddr + (uint32_t)(i * (16 * 144) + kk * 32));
#pragma unroll
            for (int j2 = 0; j2 < 2; j2++) {
                if (BM0) LDSM_X4_T(bh[j2], st + BOF + bAddr + (uint32_t)(kk * (16 * 272) + j2 * 32));
                else     LDSM_X4  (bh[j2], st + BOF + bAddr + (uint32_t)(j2 * (16 * 144) + kk * 32));
            }
            // pass 1: A_hi * B
#pragma unroll
            for (int i = 0; i < 4; i++)
#pragma unroll
                for (int j = 0; j < 4; j++)
                    MMA_F16(acc[i][j], ah[i], bh[j >> 1][(j & 1) * 2], bh[j >> 1][(j & 1) * 2 + 1]);
            // pass 2: A_lo * B
            {
                uint32_t al[4][4];
#pragma unroll
                for (int i = 0; i < 4; i++)
                    LDSM_X4(al[i], st + ALO + aAddr + (uint32_t)(i * (16 * 144) + kk * 32));
#pragma unroll
                for (int i = 0; i < 4; i++)
#pragma unroll
                    for (int j = 0; j < 4; j++)
                        MMA_F16(acc[i][j], al[i], bh[j >> 1][(j & 1) * 2], bh[j >> 1][(j & 1) * 2 + 1]);
            }
        }
        __syncthreads();
    }

    // ---- epilogue ----
    const int g = lane >> 2, t4 = lane & 3;
#pragma unroll
    for (int i = 0; i < 4; i++) {
        int m = m0 + wm * 64 + i * 16 + g;
#pragma unroll
        for (int j = 0; j < 4; j++) {
            int n = n0 + wn * 32 + j * 8 + t4 * 2;
            if (MODE == 1) {
                int ml = m - m0;
                atomicAdd(&Yf_[(size_t)ml * LDY + n],       acc[i][j][0] * SCALE_F);
                atomicAdd(&Yf_[(size_t)ml * LDY + n + 1],   acc[i][j][1] * SCALE_F);
                atomicAdd(&Yf_[(size_t)(ml + 8) * LDY + n],     acc[i][j][2] * SCALE_F);
                atomicAdd(&Yf_[(size_t)(ml + 8) * LDY + n + 1], acc[i][j][3] * SCALE_F);
            } else if (MODE == 3) {
                *reinterpret_cast<float2*>(&Yf_[(size_t)m * LDY + n]) =
                    make_float2(acc[i][j][0], acc[i][j][1]);
                *reinterpret_cast<float2*>(&Yf_[(size_t)(m + 8) * LDY + n]) =
                    make_float2(acc[i][j][2], acc[i][j][3]);
            } else if (MODE == 2) {
#pragma unroll
                for (int half = 0; half < 2; half++) {
                    size_t off = (size_t)(m + half * 8) * LDY + n;
                    *reinterpret_cast<__half2*>(&Yhi_[off]) =
                        __half2(__float2half_rn(acc[i][j][half * 2]),
                                __float2half_rn(acc[i][j][half * 2 + 1]));
                }
            } else {
                // MODE 0: hi + lo (V consumed as split A operand downstream)
#pragma unroll
                for (int half = 0; half < 2; half++) {
                    float v0 = acc[i][j][half * 2], v1 = acc[i][j][half * 2 + 1];
                    __half h0 = __float2half_rn(v0), h1 = __float2half_rn(v1);
                    size_t off = (size_t)(m + half * 8) * LDY + n;
                    *reinterpret_cast<__half2*>(&Yhi_[off]) = __half2(h0, h1);
                    *reinterpret_cast<__half2*>(&Ylo_[off]) =
                        __half2(__float2half_rn(v0 - __half2float(h0)),
                                __float2half_rn(v1 - __half2float(h1)));
                }
            }
        }
    }
}

#define SMEM_BM0 (2 * 54272)   // 108544
#define SMEM_BM1 (2 * 55296)   // 110592

// ---------------------------------------------------------------------------
extern "C" void kernel_launch(void* const* d_in, const int* in_sizes, int n_in,
                              void* d_out, int out_size) {
    const float* x = nullptr;
    const float* W_qkv = nullptr;
    const float* W_out = nullptr;
    for (int i = 0; i < n_in; i++) {
        if (in_sizes[i] == BATCH * CIN * SEQ)      x     = (const float*)d_in[i];
        else if (in_sizes[i] == C3 * CIN)          W_qkv = (const float*)d_in[i];
        else if (in_sizes[i] == CIN * CIN)         W_out = (const float*)d_in[i];
    }
    float* out = (float*)d_out;

    cudaFuncSetAttribute(hgemm<0>, cudaFuncAttributeMaxDynamicSharedMemorySize, SMEM_BM0);
    cudaFuncSetAttribute(hgemm<1>, cudaFuncAttributeMaxDynamicSharedMemorySize, SMEM_BM1);
    cudaFuncSetAttribute(hgemm<2>, cudaFuncAttributeMaxDynamicSharedMemorySize, SMEM_BM0);
    cudaFuncSetAttribute(hgemm<3>, cudaFuncAttributeMaxDynamicSharedMemorySize, SMEM_BM0);

    // Symbol addresses
    __half *pWqH, *pWqL, *pWoH, *pWoL, *pX, *pMH, *pML;
    float* pM;
    cudaGetSymbolAddress((void**)&pWqH, g_Wq_hi);
    cudaGetSymbolAddress((void**)&pWqL, g_Wq_lo);
    cudaGetSymbolAddress((void**)&pWoH, g_Wo_hi);
    cudaGetSymbolAddress((void**)&pWoL, g_Wo_lo);
    cudaGetSymbolAddress((void**)&pX,   g_x);
    cudaGetSymbolAddress((void**)&pM,   g_M);
    cudaGetSymbolAddress((void**)&pMH,  g_M_hi);
    cudaGetSymbolAddress((void**)&pML,  g_M_lo);

    // Input conversions
    split2_h<<<(C3 * CIN / 4 + 255) / 256, 256>>>(W_qkv, pWqH, pWqL, C3 * CIN / 4);
    split2_h<<<(CIN * CIN / 4 + 255) / 256, 256>>>(W_out, pWoH, pWoL, CIN * CIN / 4);
    round_h<<<(BATCH * CIN * SEQ / 4 + 255) / 256, 256>>>(x, pX, BATCH * CIN * SEQ / 4);

    // QKV projection
    hgemm<0><<<dim3(SEQ / 128, C3 / 128, BATCH), 256, SMEM_BM0>>>(nullptr);

    // Linear attention core: M = scale * V K^T, then C = M Q
    zero_M_kernel<<<512, 1024>>>();
    hgemm<1><<<dim3(1, 8, BATCH * NH), 256, SMEM_BM1>>>(nullptr);
    split2_h<<<(BATCH * NH * DH * DH / 4 + 255) / 256, 256>>>(pM, pMH, pML, BATCH * NH * DH * DH / 4);
    hgemm<2><<<dim3(SEQ / 128, 1, BATCH * NH), 256, SMEM_BM0>>>(nullptr);

    // Output projection
    hgemm<3><<<dim3(SEQ / 128, CIN / 128, BATCH), 256, SMEM_BM0>>>(out);
}

// round 16
// speedup vs baseline: 2.4304x; 1.6494x over previous
#include <cuda_runtime.h>
#include <cuda_fp16.h>
#include <cstdint>

// Problem constants
#define BATCH 4
#define SEQ   2048
#define CIN   1024
#define C3    3072
#define NH    8
#define DH    128
#define SCALE_F 0.08838834764831845f   // 1/sqrt(128)

// ---------------------------------------------------------------------------
// Scratch (device globals — no runtime allocation)
// ---------------------------------------------------------------------------
__device__ __half g_Wq[(size_t)C3 * CIN];
__device__ __half g_Wo[(size_t)CIN * CIN];
__device__ __half g_x[(size_t)BATCH * CIN * SEQ];
__device__ __half g_qkv[(size_t)BATCH * C3 * SEQ];
__device__ float  g_M[(size_t)BATCH * NH * DH * DH];
__device__ __half g_Mh[(size_t)BATCH * NH * DH * DH];
__device__ __half g_C[(size_t)BATCH * CIN * SEQ];

// ---------------------------------------------------------------------------
// PTX helpers (sm_80-era features: legal in compute_103 PTX)
// ---------------------------------------------------------------------------
__device__ __forceinline__ uint32_t smem_to_u32(const void* p) {
    uint32_t a;
    asm("{ .reg .u64 t; cvta.to.shared.u64 t, %1; cvt.u32.u64 %0, t; }" : "=r"(a) : "l"(p));
    return a;
}
#define LDSM_X4(r, addr) \
    asm volatile("ldmatrix.sync.aligned.m8n8.x4.shared.b16 {%0,%1,%2,%3}, [%4];" \
                 : "=r"((r)[0]), "=r"((r)[1]), "=r"((r)[2]), "=r"((r)[3]) : "r"(addr))
#define LDSM_X4_T(r, addr) \
    asm volatile("ldmatrix.sync.aligned.m8n8.x4.trans.shared.b16 {%0,%1,%2,%3}, [%4];" \
                 : "=r"((r)[0]), "=r"((r)[1]), "=r"((r)[2]), "=r"((r)[3]) : "r"(addr))
#define MMA_F16(c, a, b0, b1) \
    asm volatile("mma.sync.aligned.m16n8k16.row.col.f32.f16.f16.f32 " \
                 "{%0,%1,%2,%3},{%4,%5,%6,%7},{%8,%9},{%0,%1,%2,%3};" \
                 : "+f"((c)[0]), "+f"((c)[1]), "+f"((c)[2]), "+f"((c)[3]) \
                 : "r"((a)[0]), "r"((a)[1]), "r"((a)[2]), "r"((a)[3]), "r"(b0), "r"(b1))
#define CP_ASYNC16(dst, src) \
    asm volatile("cp.async.cg.shared.global [%0], [%1], 16;" :: "r"(dst), "l"(src) : "memory")
#define CP_COMMIT() asm volatile("cp.async.commit_group;" ::: "memory")
#define CP_WAIT2()  asm volatile("cp.async.wait_group 2;" ::: "memory")

// ---------------------------------------------------------------------------
// Conversions
// ---------------------------------------------------------------------------
__global__ void round_h(const float* __restrict__ src, __half* __restrict__ dst, int n4) {
    int i = blockIdx.x * blockDim.x + threadIdx.x;
    if (i >= n4) return;
    float4 v = reinterpret_cast<const float4*>(src)[i];
    __half2* dp = reinterpret_cast<__half2*>(dst);
    dp[2 * i]     = __half2(__float2half_rn(v.x), __float2half_rn(v.y));
    dp[2 * i + 1] = __half2(__float2half_rn(v.z), __float2half_rn(v.w));
}

__global__ void zero_M_kernel() {
    int i = blockIdx.x * blockDim.x + threadIdx.x;
    if (i < BATCH * NH * DH * DH) g_M[i] = 0.0f;
}

// ---------------------------------------------------------------------------
// Single-pass fp16 HMMA GEMM: Y = A_fp16 @ B_fp16 (fp32 accumulate).
// Block 128x128, 8 warps of 64x32, K-chunk 64, cp.async 3-stage, 2 CTAs/SM.
// MODE 0: qkv = Wq @ x            (B k-major/trans, EPI fp16)    grid(16,24,4)
// MODE 1: M  += scale * V @ K^T   (B n-major,       EPI atomic)  grid(1, 8,32)
// MODE 2: C  = M @ Q              (B k-major/trans, EPI fp16)    grid(16,1,32)
// MODE 3: out = Wo @ C            (B k-major/trans, EPI fp32)    grid(16, 8,4)
// ---------------------------------------------------------------------------
template <int MODE>
__global__ __launch_bounds__(256, 2) void hgemm(float* __restrict__ OutExt) {
    constexpr bool BM0   = (MODE != 1);                     // B trans (k-major) path
    constexpr int  KLEN  = (MODE == 1) ? 256 : (MODE == 2 ? 128 : 1024);
    constexpr int  LDA   = (MODE == 1) ? SEQ : (MODE == 2 ? DH : CIN);
    constexpr int  LDB   = SEQ;
    constexpr int  LDY   = (MODE == 1) ? DH : SEQ;
    // smem per stage: A[128x64] stride 144B (18432), then B
    constexpr uint32_t AOF = 0, BOF = 18432;
    constexpr uint32_t BT  = BM0 ? 17408u : 18432u;
    constexpr uint32_t STAGE = BOF + BT;                    // 35840 / 36864
    constexpr int NIT = KLEN / 64;

    extern __shared__ char smem[];
    const uint32_t sbase = smem_to_u32(smem);
    const int tid = threadIdx.x;
    const int lane = tid & 31, wid = tid >> 5;              // 8 warps
    const int wm = wid & 1, wn = wid >> 1;                  // warp grid 2(m) x 4(n)
    const int z  = blockIdx.z;
    const int m0 = (MODE == 0 || MODE == 3) ? blockIdx.y * 128 : 0;
    const int n0 = blockIdx.x * 128;
    const int kStart = (MODE == 1) ? blockIdx.y * 256 : 0;

    const __half *A_, *B_;
    __half* Yh_ = nullptr;
    float*  Yf_ = nullptr;
    if (MODE == 0) {
        A_ = g_Wq;
        B_ = g_x + (size_t)z * CIN * SEQ;
        Yh_ = g_qkv + (size_t)z * C3 * SEQ;
    } else if (MODE == 1) {
        int b = z >> 3, h = z & 7;
        A_ = g_qkv + ((size_t)b * C3 + 2 * CIN + h * DH) * SEQ;   // V
        B_ = g_qkv + ((size_t)b * C3 + CIN + h * DH) * SEQ;       // K
        Yf_ = g_M + (size_t)z * DH * DH;
    } else if (MODE == 2) {
        int b = z >> 3, h = z & 7;
        A_ = g_Mh + (size_t)z * DH * DH;
        B_ = g_qkv + ((size_t)b * C3 + h * DH) * SEQ;             // Q
        Yh_ = g_C + ((size_t)b * CIN + h * DH) * SEQ;
    } else {
        A_ = g_Wo;
        B_ = g_C + (size_t)z * CIN * SEQ;
        Yf_ = OutExt + (size_t)z * CIN * SEQ;
    }

    // ldmatrix base addresses (tile-relative); A row stride 144 B
    const uint32_t aAddr = (uint32_t)((wm * 64 + (lane & 15)) * 144 + (lane >> 4) * 16);
    uint32_t bAddr;
    if (BM0) {
        int seg = lane >> 3;
        bAddr = (uint32_t)(((seg & 1) * 8 + (lane & 7)) * 272 + (wn * 32 + (seg >> 1) * 8) * 2);
    } else {
        bAddr = (uint32_t)((wn * 32 + ((lane >> 4) << 3) + (lane & 7)) * 144 + ((lane >> 3) & 1) * 16);
    }

    float acc[4][4][4];
#pragma unroll
    for (int i = 0; i < 4; i++)
#pragma unroll
        for (int j = 0; j < 4; j++)
#pragma unroll
            for (int q = 0; q < 4; q++) acc[i][j][q] = 0.0f;

    auto fill = [&](int s) {
        const uint32_t sp = sbase + (uint32_t)((s % 3) * STAGE);
        const int k0 = kStart + s * 64;
        // A: 128 rows x 64 k = 1024 16B chunks
#pragma unroll
        for (int t = 0; t < 4; t++) {
            int c = tid + t * 256;
            int row = c >> 3, ke = (c & 7) * 8;
            CP_ASYNC16(sp + AOF + (uint32_t)(row * 144 + ke * 2),
                       A_ + (size_t)(m0 + row) * LDA + k0 + ke);
        }
        if (BM0) {
            // B: 64 k-rows x 128 n
#pragma unroll
            for (int t = 0; t < 4; t++) {
                int c = tid + t * 256;
                int row = c >> 4, ne = (c & 15) * 8;
                CP_ASYNC16(sp + BOF + (uint32_t)(row * 272 + ne * 2),
                           B_ + (size_t)(k0 + row) * LDB + n0 + ne);
            }
        } else {
            // B: 128 n-rows x 64 k
#pragma unroll
            for (int t = 0; t < 4; t++) {
                int c = tid + t * 256;
                int row = c >> 3, ke = (c & 7) * 8;
                CP_ASYNC16(sp + BOF + (uint32_t)(row * 144 + ke * 2),
                           B_ + (size_t)(n0 + row) * LDB + k0 + ke);
            }
        }
    };

    // prologue: 2 stages in flight
    fill(0); CP_COMMIT();
    fill(1); CP_COMMIT();

    for (int s = 0; s < NIT; s++) {
        if (s + 2 < NIT) fill(s + 2);
        CP_COMMIT();            // (possibly empty) group
        CP_WAIT2();             // stage s resolved
        __syncthreads();

        const uint32_t st = sbase + (uint32_t)((s % 3) * STAGE);
#pragma unroll
        for (int kk = 0; kk < 4; kk++) {
            uint32_t ah[4][4], bh[2][4];
#pragma unroll
            for (int i = 0; i < 4; i++)
                LDSM_X4(ah[i], st + AOF + aAddr + (uint32_t)(i * (16 * 144) + kk * 32));
#pragma unroll
            for (int j2 = 0; j2 < 2; j2++) {
                if (BM0) LDSM_X4_T(bh[j2], st + BOF + bAddr + (uint32_t)(kk * (16 * 272) + j2 * 32));
                else     LDSM_X4  (bh[j2], st + BOF + bAddr + (uint32_t)(j2 * (16 * 144) + kk * 32));
            }
#pragma unroll
            for (int i = 0; i < 4; i++)
#pragma unroll
                for (int j = 0; j < 4; j++)
                    MMA_F16(acc[i][j], ah[i], bh[j >> 1][(j & 1) * 2], bh[j >> 1][(j & 1) * 2 + 1]);
        }
        __syncthreads();
    }

    // ---- epilogue ----
    const int g = lane >> 2, t4 = lane & 3;
#pragma unroll
    for (int i = 0; i < 4; i++) {
        int m = m0 + wm * 64 + i * 16 + g;
#pragma unroll
        for (int j = 0; j < 4; j++) {
            int n = n0 + wn * 32 + j * 8 + t4 * 2;
            if (MODE == 1) {
                int ml = m - m0;
                atomicAdd(&Yf_[(size_t)ml * LDY + n],       acc[i][j][0] * SCALE_F);
                atomicAdd(&Yf_[(size_t)ml * LDY + n + 1],   acc[i][j][1] * SCALE_F);
                atomicAdd(&Yf_[(size_t)(ml + 8) * LDY + n],     acc[i][j][2] * SCALE_F);
                atomicAdd(&Yf_[(size_t)(ml + 8) * LDY + n + 1], acc[i][j][3] * SCALE_F);
            } else if (MODE == 3) {
                *reinterpret_cast<float2*>(&Yf_[(size_t)m * LDY + n]) =
                    make_float2(acc[i][j][0], acc[i][j][1]);
                *reinterpret_cast<float2*>(&Yf_[(size_t)(m + 8) * LDY + n]) =
                    make_float2(acc[i][j][2], acc[i][j][3]);
            } else {
#pragma unroll
                for (int half = 0; half < 2; half++) {
                    size_t off = (size_t)(m + half * 8) * LDY + n;
                    *reinterpret_cast<__half2*>(&Yh_[off]) =
                        __half2(__float2half_rn(acc[i][j][half * 2]),
                                __float2half_rn(acc[i][j][half * 2 + 1]));
                }
            }
        }
    }
}

#define SMEM_BM0 (3 * 35840)   // 107520
#define SMEM_BM1 (3 * 36864)   // 110592

// ---------------------------------------------------------------------------
extern "C" void kernel_launch(void* const* d_in, const int* in_sizes, int n_in,
                              void* d_out, int out_size) {
    const float* x = nullptr;
    const float* W_qkv = nullptr;
    const float* W_out = nullptr;
    for (int i = 0; i < n_in; i++) {
        if (in_sizes[i] == BATCH * CIN * SEQ)      x     = (const float*)d_in[i];
        else if (in_sizes[i] == C3 * CIN)          W_qkv = (const float*)d_in[i];
        else if (in_sizes[i] == CIN * CIN)         W_out = (const float*)d_in[i];
    }
    float* out = (float*)d_out;

    cudaFuncSetAttribute(hgemm<0>, cudaFuncAttributeMaxDynamicSharedMemorySize, SMEM_BM0);
    cudaFuncSetAttribute(hgemm<1>, cudaFuncAttributeMaxDynamicSharedMemorySize, SMEM_BM1);
    cudaFuncSetAttribute(hgemm<2>, cudaFuncAttributeMaxDynamicSharedMemorySize, SMEM_BM0);
    cudaFuncSetAttribute(hgemm<3>, cudaFuncAttributeMaxDynamicSharedMemorySize, SMEM_BM0);

    // Symbol addresses
    __half *pWq, *pWo, *pX, *pMh;
    float* pM;
    cudaGetSymbolAddress((void**)&pWq, g_Wq);
    cudaGetSymbolAddress((void**)&pWo, g_Wo);
    cudaGetSymbolAddress((void**)&pX,  g_x);
    cudaGetSymbolAddress((void**)&pM,  g_M);
    cudaGetSymbolAddress((void**)&pMh, g_Mh);

    // Input conversions (fp32 -> fp16)
    round_h<<<(C3 * CIN / 4 + 255) / 256, 256>>>(W_qkv, pWq, C3 * CIN / 4);
    round_h<<<(CIN * CIN / 4 + 255) / 256, 256>>>(W_out, pWo, CIN * CIN / 4);
    round_h<<<(BATCH * CIN * SEQ / 4 + 255) / 256, 256>>>(x, pX, BATCH * CIN * SEQ / 4);

    // QKV projection
    hgemm<0><<<dim3(SEQ / 128, C3 / 128, BATCH), 256, SMEM_BM0>>>(nullptr);

    // Linear attention core: M = scale * V K^T, then C = M Q
    zero_M_kernel<<<512, 1024>>>();
    hgemm<1><<<dim3(1, 8, BATCH * NH), 256, SMEM_BM1>>>(nullptr);
    round_h<<<(BATCH * NH * DH * DH / 4 + 255) / 256, 256>>>(pM, pMh, BATCH * NH * DH * DH / 4);
    hgemm<2><<<dim3(SEQ / 128, 1, BATCH * NH), 256, SMEM_BM0>>>(nullptr);

    // Output projection
    hgemm<3><<<dim3(SEQ / 128, CIN / 128, BATCH), 256, SMEM_BM0>>>(out);
}